// round 8
// baseline (speedup 1.0000x reference)
#include <cuda_runtime.h>
#include <math.h>
#include <stdint.h>
#include <stddef.h>

#define NB 64
#define NS 1024
#define ND 128
#define NG 512

// ---------------- static scratch (no allocation) ----------------
__device__ float g_Xg[(size_t)NS * NB * NG];      // [s][b][gate]
__device__ float g_hid[(size_t)NB * NS * ND];     // raw h [b][s][d]
__device__ float g_hidln[(size_t)NB * NS * ND];   // LN'd h [b][s][d]
__device__ float g_Wt[ND * ND];                   // W_att transposed [n][d']
__device__ float g_asp[NB * ND];                  // LN'd aspect emb
__device__ float g_AbT[(size_t)NB * ND * ND];     // [b][m][d']
__device__ float g_score[NB * NS];
__device__ float g_rpre[NB * ND];

// ---------------- helpers ----------------
__device__ __forceinline__ float sigf(float x) { return 1.f / (1.f + expf(-x)); }

__device__ __forceinline__ unsigned smem_u32(const void* p) {
    return (unsigned)__cvta_generic_to_shared(p);
}
__device__ __forceinline__ unsigned mapa_u32(unsigned a, unsigned rank) {
    unsigned r;
    asm("mapa.shared::cluster.u32 %0, %1, %2;" : "=r"(r) : "r"(a), "r"(rank));
    return r;
}
__device__ __forceinline__ void st_remote_f32(unsigned a, float v) {
    asm volatile("st.shared::cluster.f32 [%0], %1;" :: "r"(a), "f"(v) : "memory");
}
__device__ __forceinline__ void cluster_sync_all() {
    asm volatile("barrier.cluster.arrive.aligned;" ::: "memory");
    asm volatile("barrier.cluster.wait.aligned;" ::: "memory");
}
__device__ __forceinline__ unsigned ctarank() {
    unsigned r;
    asm("mov.u32 %0, %%cluster_ctarank;" : "=r"(r));
    return r;
}
__device__ __forceinline__ void fma2(unsigned long long& d,
                                     unsigned long long a, unsigned long long b) {
    asm("fma.rn.f32x2 %0, %1, %2, %0;" : "+l"(d) : "l"(a), "l"(b));
}

// sum over a 128-thread block; all threads get the result
__device__ __forceinline__ float blk128_sum(float v, float* red, int tid) {
    for (int o = 16; o; o >>= 1) v += __shfl_xor_sync(0xffffffffu, v, o);
    if ((tid & 31) == 0) red[tid >> 5] = v;
    __syncthreads();
    float s = red[0] + red[1] + red[2] + red[3];
    __syncthreads();
    return s;
}

// ---------------- aspect embed + LN ----------------
__global__ void k_aspect(const int* __restrict__ aspect, const float* __restrict__ emb,
                         const float* __restrict__ an_g, const float* __restrict__ an_b) {
    __shared__ float red[4];
    int b = blockIdx.x, d = threadIdx.x;
    float x = emb[(size_t)aspect[b] * ND + d];
    float m = blk128_sum(x, red, d) * (1.f / 128.f);
    float dx = x - m;
    float v = blk128_sum(dx * dx, red, d) * (1.f / 128.f);
    g_asp[b * ND + d] = dx * rsqrtf(v + 1e-5f) * an_g[d] + an_b[d];
}

__global__ void k_wt(const float* __restrict__ W_att) {
    int d = blockIdx.x, t = threadIdx.x;
    g_Wt[d * ND + t] = W_att[t * ND + d];   // g_Wt[n][d'] = W_att[d'][n]
}

// g_AbT[b][m][d'] = sum_n W_att[d'][n] * asp_b[(n-m) & 127]
__global__ void __launch_bounds__(256) k_abt() {
    __shared__ float asp_s[ND];
    int b = blockIdx.x, tid = threadIdx.x;
    if (tid < ND) asp_s[tid] = g_asp[b * ND + tid];
    __syncthreads();
    for (int o = tid; o < ND * ND; o += 256) {
        int m = o >> 7, dp = o & 127;
        float acc = 0.f;
#pragma unroll 8
        for (int n = 0; n < ND; n++)
            acc = fmaf(g_Wt[n * ND + dp], asp_s[(n - m) & 127], acc);
        g_AbT[(size_t)b * ND * ND + o] = acc;
    }
}

// ---------------- input projection GEMM ----------------
__global__ void __launch_bounds__(256) k_xg(const int* __restrict__ new_list,
                                            const float* __restrict__ emb,
                                            const float* __restrict__ W_ih,
                                            const float* __restrict__ b_ih,
                                            const float* __restrict__ b_hh) {
    __shared__ float As[64][65];
    __shared__ float Bs[64][65];
    __shared__ int toks[64];
    int s = blockIdx.y, c0 = blockIdx.x * 64, tid = threadIdx.x;
    int tx = tid & 15, ty = tid >> 4;
    if (tid < 64) toks[tid] = new_list[tid * NS + s];
    float acc[4][4] = {};
    __syncthreads();
    for (int kk = 0; kk < ND; kk += 64) {
#pragma unroll
        for (int i = 0; i < 4; i++) {
            int idx = tid + i * 256, r = idx >> 4, q = idx & 15;
            float4 v = ((const float4*)(emb + (size_t)toks[r] * ND + kk))[q];
            As[r][q * 4 + 0] = v.x; As[r][q * 4 + 1] = v.y;
            As[r][q * 4 + 2] = v.z; As[r][q * 4 + 3] = v.w;
            float4 w = ((const float4*)(W_ih + (size_t)(c0 + r) * ND + kk))[q];
            Bs[r][q * 4 + 0] = w.x; Bs[r][q * 4 + 1] = w.y;
            Bs[r][q * 4 + 2] = w.z; Bs[r][q * 4 + 3] = w.w;
        }
        __syncthreads();
#pragma unroll 8
        for (int k = 0; k < 64; k++) {
            float a[4], bb[4];
#pragma unroll
            for (int i = 0; i < 4; i++) a[i] = As[ty + i * 16][k];
#pragma unroll
            for (int j = 0; j < 4; j++) bb[j] = Bs[tx + j * 16][k];
#pragma unroll
            for (int i = 0; i < 4; i++)
#pragma unroll
                for (int j = 0; j < 4; j++) acc[i][j] = fmaf(a[i], bb[j], acc[i][j]);
        }
        __syncthreads();
    }
#pragma unroll
    for (int i = 0; i < 4; i++) {
        int r = ty + i * 16;
        size_t rowbase = ((size_t)s * NB + r) * NG;
#pragma unroll
        for (int j = 0; j < 4; j++) {
            int col = c0 + tx + j * 16;
            g_Xg[rowbase + col] = acc[i][j] + b_ih[col] + b_hh[col];
        }
    }
}

// ---------------- LSTM recurrence: 2-CTA cluster per batch row ----------------
// Each thread owns one W_hh row (register-resident, 64 x f32x2). CTA rank 0
// computes gates i,f (rows 0..255); rank 1 computes g,o (rows 256..511).
__global__ void __cluster_dims__(2, 1, 1) __launch_bounds__(256, 1)
k_lstm(const float* __restrict__ W_hh) {
    __shared__ float h_sh[ND];          // current hidden state
    __shared__ float gbuf[2][512];      // parity double-buffered gates
    int tid = threadIdx.x;
    unsigned rank = ctarank();
    int b = blockIdx.x >> 1;
    int base = (int)rank * 256;

    // register-resident W row for this thread (128 floats = 64 f32x2)
    unsigned long long w[64];
    {
        const unsigned long long* Wg =
            (const unsigned long long*)(W_hh + (size_t)(base + tid) * ND);
#pragma unroll
        for (int j = 0; j < 64; j++) w[j] = Wg[j];
    }
    if (tid < ND) h_sh[tid] = 0.f;
    __syncthreads();

    unsigned peer = mapa_u32(smem_u32(&gbuf[0][0]), rank ^ 1u);
    float c = 0.f;
    float* hout = g_hid + (size_t)b * NS * ND;
    const float* xgp = g_Xg + (size_t)b * NG + base + tid;

    float xg = xgp[0];                  // prefetch step 0
    for (int s = 0; s < NS; s++) {
        // matvec: acc2 = sum_j w[j] * h2[j]   (f32x2, exact fp32)
        unsigned long long acc2 = 0ull;  // (+0.f, +0.f)
        const unsigned long long* hv = (const unsigned long long*)h_sh;
#pragma unroll
        for (int j = 0; j < 64; j++) fma2(acc2, w[j], hv[j]);
        float lo = __uint_as_float((unsigned)(acc2 & 0xffffffffull));
        float hi = __uint_as_float((unsigned)(acc2 >> 32));
        float gv = lo + hi + xg;

        // prefetch next step's Xg (latency hidden by exchange + barrier)
        if (s + 1 < NS) xg = xgp[(size_t)(s + 1) * NB * NG];

        int p = s & 1;
        gbuf[p][base + tid] = gv;
        st_remote_f32(peer + (unsigned)(p * 512 + base + tid) * 4u, gv);
        cluster_sync_all();

        if (tid < ND) {
            const float* g = gbuf[p];
            float gi = g[tid], gf = g[128 + tid], gg = g[256 + tid], go = g[384 + tid];
            c = sigf(gf) * c + sigf(gi) * tanhf(gg);
            float h = sigf(go) * tanhf(c);
            h_sh[tid] = h;
            if (rank == 0) hout[s * ND + tid] = h;
        }
        __syncthreads();
    }
    cluster_sync_all();  // keep DSMEM alive until peer's remote stores land
}

// ---------------- LayerNorm of hidden states ----------------
__global__ void k_ln(const float* __restrict__ hn_g, const float* __restrict__ hn_b) {
    __shared__ float red[4];
    int s = blockIdx.x, b = blockIdx.y, d = threadIdx.x;
    size_t off = ((size_t)b * NS + s) * ND;
    float x = g_hid[off + d];
    float m = blk128_sum(x, red, d) * (1.f / 128.f);
    float dx = x - m;
    float v = blk128_sum(dx * dx, red, d) * (1.f / 128.f);
    g_hidln[off + d] = dx * rsqrtf(v + 1e-5f) * hn_g[d] + hn_b[d];
}

// ---------------- attention scores (circular conv folded into A_b) -----------
#define SCORE_SMEM_BYTES ((16384 + 128 + 128) * 4)
__global__ void __launch_bounds__(128) k_score(const float* __restrict__ new_mask,
                                               const float* __restrict__ W_aw) {
    extern __shared__ float s4[];
    float* Ab = s4;            // 128x128
    float* hrow = s4 + 16384;  // 128
    float* waw = s4 + 16512;   // 128
    __shared__ float red[4];
    int b = blockIdx.y, s0 = blockIdx.x * 128, t = threadIdx.x;
    for (int i = t; i < 16384; i += 128) Ab[i] = g_AbT[(size_t)b * 16384 + i];
    waw[t] = W_aw[t];
    __syncthreads();
    for (int s = s0; s < s0 + 128; s++) {
        hrow[t] = g_hidln[((size_t)b * NS + s) * ND + t];
        __syncthreads();
        float acc = 0.f;
#pragma unroll 8
        for (int m = 0; m < ND; m++) acc = fmaf(hrow[m], Ab[m * ND + t], acc);
        float tot = blk128_sum(waw[t] * tanhf(acc), red, t);
        if (t == 0) g_score[b * NS + s] = tot * new_mask[b * NS + s];
        // blk128_sum's trailing __syncthreads protects hrow reuse
    }
}

// ---------------- softmax over S + weighted sum of hidln ----------------
__global__ void __launch_bounds__(256) k_swsum() {
    __shared__ float sw[NS];
    __shared__ float red[8];
    __shared__ float part[256];
    int b = blockIdx.x, t = threadIdx.x;
    const float* sc = g_score + b * NS;
    float mx = -1e30f;
    for (int s = t; s < NS; s += 256) mx = fmaxf(mx, sc[s]);
    for (int o = 16; o; o >>= 1) mx = fmaxf(mx, __shfl_xor_sync(~0u, mx, o));
    if ((t & 31) == 0) red[t >> 5] = mx;
    __syncthreads();
    mx = red[0];
#pragma unroll
    for (int i = 1; i < 8; i++) mx = fmaxf(mx, red[i]);
    __syncthreads();
    float sum = 0.f;
    for (int s = t; s < NS; s += 256) { float e = expf(sc[s] - mx); sw[s] = e; sum += e; }
    for (int o = 16; o; o >>= 1) sum += __shfl_xor_sync(~0u, sum, o);
    if ((t & 31) == 0) red[t >> 5] = sum;
    __syncthreads();
    float tot = 0.f;
#pragma unroll
    for (int i = 0; i < 8; i++) tot += red[i];
    // weighted sum: thread (half, d)
    int d = t & 127, half = t >> 7;
    float acc = 0.f;
    const float* hp = g_hidln + (size_t)b * NS * ND + d;
    for (int s = half * 512; s < half * 512 + 512; s++)
        acc = fmaf(sw[s], hp[(size_t)s * ND], acc);
    part[t] = acc;
    __syncthreads();
    if (t < 128) g_rpre[b * ND + t] = (part[t] + part[t + 128]) / tot;
}

// ---------------- output head ----------------
__global__ void __launch_bounds__(128) k_head(const float* __restrict__ W_rout,
                                              const float* __restrict__ W_hout,
                                              const float* __restrict__ W_cls,
                                              const float* __restrict__ b_cls,
                                              float* __restrict__ out) {
    __shared__ float rp[ND], hL[ND], red[4];
    int b = blockIdx.x, d = threadIdx.x;
    rp[d] = g_rpre[b * ND + d];
    hL[d] = g_hid[((size_t)b * NS + (NS - 1)) * ND + d];
    __syncthreads();
    float a = 0.f;
#pragma unroll 4
    for (int k = 0; k < ND; k++) {
        a = fmaf(W_rout[d * ND + k], rp[k], a);
        a = fmaf(W_hout[d * ND + k], hL[k], a);
    }
    float r = tanhf(a);
    out[2 * NB + b * ND + d] = r;  // r tensor follows the (B,2) result tensor
    float l0 = blk128_sum(r * W_cls[d], red, d);
    float l1 = blk128_sum(r * W_cls[ND + d], red, d);
    if (d == 0) {
        l0 += b_cls[0]; l1 += b_cls[1];
        float m = fmaxf(l0, l1);
        float e0 = expf(l0 - m), e1 = expf(l1 - m), inv = 1.f / (e0 + e1);
        out[b * 2] = e0 * inv;
        out[b * 2 + 1] = e1 * inv;
    }
}

// ---------------- launch ----------------
extern "C" void kernel_launch(void* const* d_in, const int* in_sizes, int n_in,
                              void* d_out, int out_size) {
    const int*   new_list = (const int*)  d_in[0];
    const float* new_mask = (const float*)d_in[1];
    const int*   aspect   = (const int*)  d_in[2];
    // d_in[3] = gpunum (unused)
    const float* emb   = (const float*)d_in[4];
    const float* W_ih  = (const float*)d_in[5];
    const float* W_hh  = (const float*)d_in[6];
    const float* b_ih  = (const float*)d_in[7];
    const float* b_hh  = (const float*)d_in[8];
    const float* an_g  = (const float*)d_in[9];
    const float* an_b  = (const float*)d_in[10];
    const float* hn_g  = (const float*)d_in[11];
    const float* hn_b  = (const float*)d_in[12];
    const float* W_att = (const float*)d_in[13];
    const float* W_aw  = (const float*)d_in[14];
    const float* W_rout= (const float*)d_in[15];
    const float* W_hout= (const float*)d_in[16];
    const float* W_cls = (const float*)d_in[17];
    const float* b_cls = (const float*)d_in[18];
    float* out = (float*)d_out;

    cudaFuncSetAttribute(k_score, cudaFuncAttributeMaxDynamicSharedMemorySize, SCORE_SMEM_BYTES);

    k_aspect<<<NB, 128>>>(aspect, emb, an_g, an_b);
    k_wt<<<ND, ND>>>(W_att);
    k_abt<<<NB, 256>>>();
    k_xg<<<dim3(8, NS), 256>>>(new_list, emb, W_ih, b_ih, b_hh);
    k_lstm<<<NB * 2, 256>>>(W_hh);
    k_ln<<<dim3(NS, NB), 128>>>(hn_g, hn_b);
    k_score<<<dim3(8, NB), 128, SCORE_SMEM_BYTES>>>(new_mask, W_aw);
    k_swsum<<<NB, 256>>>();
    k_head<<<NB, 128>>>(W_rout, W_hout, W_cls, b_cls, out);
}

// round 10
// speedup vs baseline: 1.2616x; 1.2616x over previous
#include <cuda_runtime.h>
#include <math.h>
#include <stdint.h>
#include <stddef.h>

#define NB 64
#define NS 1024
#define ND 128
#define NG 512

// ---------------- static scratch (no allocation) ----------------
__device__ float g_Xg[(size_t)NS * NB * NG];      // [s][b][gate]
__device__ float g_hid[(size_t)NB * NS * ND];     // raw h [b][s][d]
__device__ float g_hidln[(size_t)NB * NS * ND];   // LN'd h [b][s][d]
__device__ float g_Wt[ND * ND];                   // W_att transposed [n][d']
__device__ float g_asp[NB * ND];                  // LN'd aspect emb
__device__ float g_AbT[(size_t)NB * ND * ND];     // [b][m][d']
__device__ float g_score[NB * NS];
__device__ float g_rpre[NB * ND];

// ---------------- helpers ----------------
// EXACT activations (libm) — used in the recurrence where errors compound.
__device__ __forceinline__ float sigf(float x) { return 1.f / (1.f + expf(-x)); }
// fast activations — one-shot use only (post-recurrence kernels)
__device__ __forceinline__ float ftanh(float x) {
    return fmaf(2.f, __fdividef(1.f, 1.f + __expf(-2.f * x)), -1.f);
}

__device__ __forceinline__ unsigned smem_u32(const void* p) {
    return (unsigned)__cvta_generic_to_shared(p);
}
__device__ __forceinline__ unsigned mapa_u32(unsigned a, unsigned rank) {
    unsigned r;
    asm("mapa.shared::cluster.u32 %0, %1, %2;" : "=r"(r) : "r"(a), "r"(rank));
    return r;
}
__device__ __forceinline__ void cluster_sync_all() {
    asm volatile("barrier.cluster.arrive.aligned;" ::: "memory");
    asm volatile("barrier.cluster.wait.aligned;" ::: "memory");
}
__device__ __forceinline__ unsigned ctarank() {
    unsigned r;
    asm("mov.u32 %0, %%cluster_ctarank;" : "=r"(r));
    return r;
}
__device__ __forceinline__ void fma2(unsigned long long& d,
                                     unsigned long long a, unsigned long long b) {
    asm("fma.rn.f32x2 %0, %1, %2, %0;" : "+l"(d) : "l"(a), "l"(b));
}
__device__ __forceinline__ unsigned long long pack2(float x, float y) {
    unsigned long long r;
    asm("mov.b64 %0, {%1, %2};" : "=l"(r) : "f"(x), "f"(y));
    return r;
}
__device__ __forceinline__ float2 unpk(unsigned long long v) {
    float2 r;
    asm("mov.b64 {%0, %1}, %2;" : "=f"(r.x), "=f"(r.y) : "l"(v));
    return r;
}
__device__ __forceinline__ void lds_v2u64(unsigned a, unsigned long long& x,
                                          unsigned long long& y) {
    asm("ld.shared.v2.u64 {%0, %1}, [%2];" : "=l"(x), "=l"(y) : "r"(a));
}
__device__ __forceinline__ void st_async_f32(unsigned a, float v, unsigned mbar) {
    asm volatile("st.async.shared::cluster.mbarrier::complete_tx::bytes.b32 [%0], %1, [%2];"
                 :: "r"(a), "r"(__float_as_uint(v)), "r"(mbar) : "memory");
}
#define MBAR_INIT(a, n) \
    asm volatile("mbarrier.init.shared.b64 [%0], %1;" :: "r"(a), "r"(n) : "memory")
#define MBAR_EXPECT(a, tx) \
    asm volatile("mbarrier.arrive.expect_tx.shared.b64 _, [%0], %1;" :: "r"(a), "r"(tx) : "memory")
__device__ __forceinline__ void mbar_wait(unsigned a, unsigned parity) {
    asm volatile("{\n\t.reg .pred P;\n"
                 "W%=:\n\tmbarrier.try_wait.parity.acquire.cta.shared::cta.b64 P, [%0], %1, 0x989680;\n"
                 "\t@P bra.uni D%=;\n\tbra.uni W%=;\nD%=:\n\t}"
                 :: "r"(a), "r"(parity) : "memory");
}

// sum over a 128-thread block; all threads get the result
__device__ __forceinline__ float blk128_sum(float v, float* red, int tid) {
    for (int o = 16; o; o >>= 1) v += __shfl_xor_sync(0xffffffffu, v, o);
    if ((tid & 31) == 0) red[tid >> 5] = v;
    __syncthreads();
    float s = red[0] + red[1] + red[2] + red[3];
    __syncthreads();
    return s;
}

// ---------------- aspect embed + LN ----------------
__global__ void k_aspect(const int* __restrict__ aspect, const float* __restrict__ emb,
                         const float* __restrict__ an_g, const float* __restrict__ an_b) {
    __shared__ float red[4];
    int b = blockIdx.x, d = threadIdx.x;
    float x = emb[(size_t)aspect[b] * ND + d];
    float m = blk128_sum(x, red, d) * (1.f / 128.f);
    float dx = x - m;
    float v = blk128_sum(dx * dx, red, d) * (1.f / 128.f);
    g_asp[b * ND + d] = dx * rsqrtf(v + 1e-5f) * an_g[d] + an_b[d];
}

__global__ void k_wt(const float* __restrict__ W_att) {
    int d = blockIdx.x, t = threadIdx.x;
    g_Wt[d * ND + t] = W_att[t * ND + d];   // g_Wt[n][d'] = W_att[d'][n]
}

// g_AbT[b][m][d'] = sum_n W_att[d'][n] * asp_b[(n-m) & 127]
__global__ void __launch_bounds__(256) k_abt() {
    __shared__ float asp_s[ND];
    int b = blockIdx.x, tid = threadIdx.x;
    if (tid < ND) asp_s[tid] = g_asp[b * ND + tid];
    __syncthreads();
    for (int o = tid; o < ND * ND; o += 256) {
        int m = o >> 7, dp = o & 127;
        float acc = 0.f;
#pragma unroll 8
        for (int n = 0; n < ND; n++)
            acc = fmaf(g_Wt[n * ND + dp], asp_s[(n - m) & 127], acc);
        g_AbT[(size_t)b * ND * ND + o] = acc;
    }
}

// ---------------- input projection GEMM (f32x2) ----------------
// tile: 64 batch rows x 128 gate cols, K=128 in 4 chunks of 32, k-major smem.
__global__ void __launch_bounds__(256) k_xg(const int* __restrict__ new_list,
                                            const float* __restrict__ emb,
                                            const float* __restrict__ W_ih,
                                            const float* __restrict__ b_ih,
                                            const float* __restrict__ b_hh) {
    __shared__ float As[32][76];    // As[k][r]
    __shared__ float Bs[32][140];   // Bs[k][c]
    __shared__ int toks[64];
    int s = blockIdx.y, c0 = blockIdx.x * 128, tid = threadIdx.x;
    int tx = tid & 15, ty = tid >> 4;
    if (tid < 64) toks[tid] = new_list[tid * NS + s];
    unsigned long long accA[4][2] = {{0ull,0ull},{0ull,0ull},{0ull,0ull},{0ull,0ull}};
    unsigned long long accB[4][2] = {{0ull,0ull},{0ull,0ull},{0ull,0ull},{0ull,0ull}};
    __syncthreads();
    for (int kk = 0; kk < ND; kk += 32) {
#pragma unroll
        for (int i = 0; i < 2; i++) {           // A: 512 float4
            int idx = tid + i * 256;
            int r = idx >> 3, q = idx & 7;
            float4 v = ((const float4*)(emb + (size_t)toks[r] * ND + kk))[q];
            As[q * 4 + 0][r] = v.x; As[q * 4 + 1][r] = v.y;
            As[q * 4 + 2][r] = v.z; As[q * 4 + 3][r] = v.w;
        }
#pragma unroll
        for (int i = 0; i < 4; i++) {           // B: 1024 float4
            int idx = tid + i * 256;
            int cc = idx >> 3, q = idx & 7;
            float4 v = ((const float4*)(W_ih + (size_t)(c0 + cc) * ND + kk))[q];
            Bs[q * 4 + 0][cc] = v.x; Bs[q * 4 + 1][cc] = v.y;
            Bs[q * 4 + 2][cc] = v.z; Bs[q * 4 + 3][cc] = v.w;
        }
        __syncthreads();
#pragma unroll
        for (int k = 0; k < 32; k++) {
            float4 a4 = *(const float4*)&As[k][ty * 4];
            unsigned long long bA0, bA1, bB0, bB1;
            lds_v2u64(smem_u32(&Bs[k][tx * 4]), bA0, bA1);
            lds_v2u64(smem_u32(&Bs[k][64 + tx * 4]), bB0, bB1);
            unsigned long long ad;
            ad = pack2(a4.x, a4.x);
            fma2(accA[0][0], ad, bA0); fma2(accA[0][1], ad, bA1);
            fma2(accB[0][0], ad, bB0); fma2(accB[0][1], ad, bB1);
            ad = pack2(a4.y, a4.y);
            fma2(accA[1][0], ad, bA0); fma2(accA[1][1], ad, bA1);
            fma2(accB[1][0], ad, bB0); fma2(accB[1][1], ad, bB1);
            ad = pack2(a4.z, a4.z);
            fma2(accA[2][0], ad, bA0); fma2(accA[2][1], ad, bA1);
            fma2(accB[2][0], ad, bB0); fma2(accB[2][1], ad, bB1);
            ad = pack2(a4.w, a4.w);
            fma2(accA[3][0], ad, bA0); fma2(accA[3][1], ad, bA1);
            fma2(accB[3][0], ad, bB0); fma2(accB[3][1], ad, bB1);
        }
        __syncthreads();
    }
    // bias
    float4 biasA, biasB;
    {
        float4 i1 = ((const float4*)(b_ih + c0))[tx];
        float4 h1 = ((const float4*)(b_hh + c0))[tx];
        biasA = make_float4(i1.x + h1.x, i1.y + h1.y, i1.z + h1.z, i1.w + h1.w);
        float4 i2 = ((const float4*)(b_ih + c0 + 64))[tx];
        float4 h2 = ((const float4*)(b_hh + c0 + 64))[tx];
        biasB = make_float4(i2.x + h2.x, i2.y + h2.y, i2.z + h2.z, i2.w + h2.w);
    }
#pragma unroll
    for (int i = 0; i < 4; i++) {
        int r = ty * 4 + i;
        float* o = g_Xg + ((size_t)s * NB + r) * NG + c0;
        float2 p0 = unpk(accA[i][0]), p1 = unpk(accA[i][1]);
        ((float4*)(o + tx * 4))[0] =
            make_float4(p0.x + biasA.x, p0.y + biasA.y, p1.x + biasA.z, p1.y + biasA.w);
        float2 q0 = unpk(accB[i][0]), q1 = unpk(accB[i][1]);
        ((float4*)(o + 64 + tx * 4))[0] =
            make_float4(q0.x + biasB.x, q0.y + biasB.y, q1.x + biasB.z, q1.y + biasB.w);
    }
}

// ---------------- LSTM recurrence: 2-CTA cluster, mbarrier h-exchange --------
// CTA rank r computes ALL FOUR gates for d in [r*64, r*64+64): W_hh rows
// {g*128 + r*64 + dl}. Only h (64 floats/CTA) crosses the cluster, via
// st.async + mbarrier complete_tx (512 B = 64 self + 64 peer stores per CTA).
// Gate activations are EXACT libm (fast __expf drifts systematically over the
// 1024-step recurrence: round-9 failure at 2e-2 rel err).
__global__ void __cluster_dims__(2, 1, 1) __launch_bounds__(256, 1)
k_lstm(const float* __restrict__ W_hh) {
    __shared__ float h_buf[2][ND];                    // parity-buffered hidden
    __shared__ float gl[256];                         // local gate pre-acts
    __shared__ __align__(8) unsigned long long mbar[2];
    int tid = threadIdx.x;
    unsigned rank = ctarank();
    int b = blockIdx.x >> 1;
    int gidx = tid >> 6, dl = tid & 63;
    int row = gidx * 128 + (int)rank * 64 + dl;       // W_hh row / Xg col

    unsigned long long w[64];
    {
        const unsigned long long* Wg = (const unsigned long long*)(W_hh + (size_t)row * ND);
#pragma unroll
        for (int j = 0; j < 64; j++) w[j] = Wg[j];
    }
    if (tid < ND) h_buf[0][tid] = 0.f;
    unsigned mb[2] = { smem_u32(&mbar[0]), smem_u32(&mbar[1]) };
    if (tid == 0) {
        MBAR_INIT(mb[0], 1); MBAR_INIT(mb[1], 1);
        MBAR_EXPECT(mb[0], 512); MBAR_EXPECT(mb[1], 512);
    }
    __syncthreads();
    cluster_sync_all();   // barriers + h_buf[0] visible cluster-wide

    // gate threads' store targets (self + peer copies of h[d])
    int d = (int)rank * 64 + dl;                      // valid for tid<64
    unsigned selfH[2], peerH[2], selfM[2], peerM[2];
#pragma unroll
    for (int q = 0; q < 2; q++) {
        unsigned a = smem_u32(&h_buf[q][d]);
        selfH[q] = mapa_u32(a, rank);  peerH[q] = mapa_u32(a, rank ^ 1u);
        selfM[q] = mapa_u32(mb[q], rank); peerM[q] = mapa_u32(mb[q], rank ^ 1u);
    }

    int ph[2] = {0, 0};
    float c = 0.f;
    float* hout = g_hid + (size_t)b * NS * ND;
    const float* xgp = g_Xg + (size_t)b * NG + row;
    float xg = xgp[0];

    for (int s = 0; s < NS; s++) {
        int q = s & 1, qn = q ^ 1;
        unsigned long long acc2 = 0ull;
        unsigned hv = smem_u32(&h_buf[q][0]);
#pragma unroll
        for (int j = 0; j < 32; j++) {
            unsigned long long h0, h1;
            lds_v2u64(hv + j * 16, h0, h1);
            fma2(acc2, w[2 * j], h0);
            fma2(acc2, w[2 * j + 1], h1);
        }
        float2 a2 = unpk(acc2);
        float gv = a2.x + a2.y + xg;
        if (s + 1 < NS) xg = xgp[(size_t)(s + 1) * NB * NG];
        gl[tid] = gv;
        __syncthreads();                               // bar1: gl + h reads done
        if (tid < 64) {
            float gi = gl[tid], gf = gl[64 + tid], gg = gl[128 + tid], go = gl[192 + tid];
            c = sigf(gf) * c + sigf(gi) * tanhf(gg);   // EXACT libm
            float h = sigf(go) * tanhf(c);
            st_async_f32(selfH[qn], h, selfM[qn]);
            st_async_f32(peerH[qn], h, peerM[qn]);
            hout[s * ND + d] = h;
        }
        mbar_wait(mb[qn], (unsigned)ph[qn]);           // all 128 h values landed
        ph[qn] ^= 1;
        if (tid == 0) MBAR_EXPECT(mb[qn], 512);        // re-arm for step s+2
    }
    cluster_sync_all();  // keep CTA alive until all cluster async traffic done
}

// ---------------- LayerNorm of hidden states ----------------
__global__ void k_ln(const float* __restrict__ hn_g, const float* __restrict__ hn_b) {
    __shared__ float red[4];
    int s = blockIdx.x, b = blockIdx.y, d = threadIdx.x;
    size_t off = ((size_t)b * NS + s) * ND;
    float x = g_hid[off + d];
    float m = blk128_sum(x, red, d) * (1.f / 128.f);
    float dx = x - m;
    float v = blk128_sum(dx * dx, red, d) * (1.f / 128.f);
    g_hidln[off + d] = dx * rsqrtf(v + 1e-5f) * hn_g[d] + hn_b[d];
}

// ---------------- attention scores (circular conv folded into A_b) -----------
#define SCORE_SMEM_BYTES ((16384 + 128 + 128) * 4)
__global__ void __launch_bounds__(128) k_score(const float* __restrict__ new_mask,
                                               const float* __restrict__ W_aw) {
    extern __shared__ float s4[];
    float* Ab = s4;            // 128x128
    float* hrow = s4 + 16384;  // 128
    float* waw = s4 + 16512;   // 128
    __shared__ float red[4];
    int b = blockIdx.y, s0 = blockIdx.x * 128, t = threadIdx.x;
    for (int i = t; i < 16384; i += 128) Ab[i] = g_AbT[(size_t)b * 16384 + i];
    waw[t] = W_aw[t];
    __syncthreads();
    for (int s = s0; s < s0 + 128; s++) {
        hrow[t] = g_hidln[((size_t)b * NS + s) * ND + t];
        __syncthreads();
        float acc = 0.f;
#pragma unroll 8
        for (int m = 0; m < ND; m++) acc = fmaf(hrow[m], Ab[m * ND + t], acc);
        float tot = blk128_sum(waw[t] * ftanh(acc), red, t);
        if (t == 0) g_score[b * NS + s] = tot * new_mask[b * NS + s];
        // blk128_sum's trailing __syncthreads protects hrow reuse
    }
}

// ---------------- softmax over S + weighted sum of hidln ----------------
__global__ void __launch_bounds__(256) k_swsum() {
    __shared__ float sw[NS];
    __shared__ float red[8];
    __shared__ float part[256];
    int b = blockIdx.x, t = threadIdx.x;
    const float* sc = g_score + b * NS;
    float mx = -1e30f;
    for (int s = t; s < NS; s += 256) mx = fmaxf(mx, sc[s]);
    for (int o = 16; o; o >>= 1) mx = fmaxf(mx, __shfl_xor_sync(~0u, mx, o));
    if ((t & 31) == 0) red[t >> 5] = mx;
    __syncthreads();
    mx = red[0];
#pragma unroll
    for (int i = 1; i < 8; i++) mx = fmaxf(mx, red[i]);
    __syncthreads();
    float sum = 0.f;
    for (int s = t; s < NS; s += 256) { float e = __expf(sc[s] - mx); sw[s] = e; sum += e; }
    for (int o = 16; o; o >>= 1) sum += __shfl_xor_sync(~0u, sum, o);
    if ((t & 31) == 0) red[t >> 5] = sum;
    __syncthreads();
    float tot = 0.f;
#pragma unroll
    for (int i = 0; i < 8; i++) tot += red[i];
    int d = t & 127, half = t >> 7;
    float acc = 0.f;
    const float* hp = g_hidln + (size_t)b * NS * ND + d;
    for (int s = half * 512; s < half * 512 + 512; s++)
        acc = fmaf(sw[s], hp[(size_t)s * ND], acc);
    part[t] = acc;
    __syncthreads();
    if (t < 128) g_rpre[b * ND + t] = (part[t] + part[t + 128]) / tot;
}

// ---------------- output head ----------------
__global__ void __launch_bounds__(128) k_head(const float* __restrict__ W_rout,
                                              const float* __restrict__ W_hout,
                                              const float* __restrict__ W_cls,
                                              const float* __restrict__ b_cls,
                                              float* __restrict__ out) {
    __shared__ float rp[ND], hL[ND], red[4];
    int b = blockIdx.x, d = threadIdx.x;
    rp[d] = g_rpre[b * ND + d];
    hL[d] = g_hid[((size_t)b * NS + (NS - 1)) * ND + d];
    __syncthreads();
    float a = 0.f;
#pragma unroll 4
    for (int k = 0; k < ND; k++) {
        a = fmaf(W_rout[d * ND + k], rp[k], a);
        a = fmaf(W_hout[d * ND + k], hL[k], a);
    }
    float r = tanhf(a);
    out[2 * NB + b * ND + d] = r;  // r tensor follows the (B,2) result tensor
    float l0 = blk128_sum(r * W_cls[d], red, d);
    float l1 = blk128_sum(r * W_cls[ND + d], red, d);
    if (d == 0) {
        l0 += b_cls[0]; l1 += b_cls[1];
        float m = fmaxf(l0, l1);
        float e0 = expf(l0 - m), e1 = expf(l1 - m), inv = 1.f / (e0 + e1);
        out[b * 2] = e0 * inv;
        out[b * 2 + 1] = e1 * inv;
    }
}

// ---------------- launch ----------------
extern "C" void kernel_launch(void* const* d_in, const int* in_sizes, int n_in,
                              void* d_out, int out_size) {
    const int*   new_list = (const int*)  d_in[0];
    const float* new_mask = (const float*)d_in[1];
    const int*   aspect   = (const int*)  d_in[2];
    // d_in[3] = gpunum (unused)
    const float* emb   = (const float*)d_in[4];
    const float* W_ih  = (const float*)d_in[5];
    const float* W_hh  = (const float*)d_in[6];
    const float* b_ih  = (const float*)d_in[7];
    const float* b_hh  = (const float*)d_in[8];
    const float* an_g  = (const float*)d_in[9];
    const float* an_b  = (const float*)d_in[10];
    const float* hn_g  = (const float*)d_in[11];
    const float* hn_b  = (const float*)d_in[12];
    const float* W_att = (const float*)d_in[13];
    const float* W_aw  = (const float*)d_in[14];
    const float* W_rout= (const float*)d_in[15];
    const float* W_hout= (const float*)d_in[16];
    const float* W_cls = (const float*)d_in[17];
    const float* b_cls = (const float*)d_in[18];
    float* out = (float*)d_out;

    cudaFuncSetAttribute(k_score, cudaFuncAttributeMaxDynamicSharedMemorySize, SCORE_SMEM_BYTES);

    k_aspect<<<NB, 128>>>(aspect, emb, an_g, an_b);
    k_wt<<<ND, ND>>>(W_att);
    k_abt<<<NB, 256>>>();
    k_xg<<<dim3(4, NS), 256>>>(new_list, emb, W_ih, b_ih, b_hh);
    k_lstm<<<NB * 2, 256>>>(W_hh);
    k_ln<<<dim3(NS, NB), 128>>>(hn_g, hn_b);
    k_score<<<dim3(8, NB), 128, SCORE_SMEM_BYTES>>>(new_mask, W_aw);
    k_swsum<<<NB, 256>>>();
    k_head<<<NB, 128>>>(W_rout, W_hout, W_cls, b_cls, out);
}